// round 13
// baseline (speedup 1.0000x reference)
#include <cuda_runtime.h>
#include <cuda_bf16.h>
#include <cstdint>

#define DHEAD 128

// Scratch (no runtime allocation allowed)
__device__ __nv_bfloat16 g_Abf[8192 * DHEAD];
__device__ float g_xsq[8192];
__device__ float g_gsq[16384];
// B in mma-fragment layout: [n16 block p][ks][lane] x 16B
__device__ uint4 g_Bfrag[1024 * 8 * 32];

__device__ __forceinline__ uint32_t smem_u32(const void* p) {
    uint32_t a;
    asm("{ .reg .u64 t; cvta.to.shared.u64 t, %1; cvt.u32.u64 %0, t; }" : "=r"(a) : "l"(p));
    return a;
}

// ---------------- Kernel 1: X fp32 -> bf16 + row norms ----------------
__global__ void __launch_bounds__(256) convert_x_kernel(const float* __restrict__ X, int n_img)
{
    int gw = (blockIdx.x * blockDim.x + threadIdx.x) >> 5;
    int lane = threadIdx.x & 31;
    if (gw >= n_img) return;
    const float4* src = (const float4*)(X + (size_t)gw * DHEAD);
    uint2* dst = (uint2*)(g_Abf + (size_t)gw * DHEAD);
    float4 v = src[lane];
    float s = v.x * v.x + v.y * v.y + v.z * v.z + v.w * v.w;
    #pragma unroll
    for (int o = 16; o > 0; o >>= 1) s += __shfl_xor_sync(0xFFFFFFFFu, s, o);
    __nv_bfloat162 p0 = __float22bfloat162_rn(make_float2(v.x, v.y));
    __nv_bfloat162 p1 = __float22bfloat162_rn(make_float2(v.z, v.w));
    uint2 o2;
    o2.x = *reinterpret_cast<uint32_t*>(&p0);
    o2.y = *reinterpret_cast<uint32_t*>(&p1);
    dst[lane] = o2;
    if (lane == 0) g_xsq[gw] = s;
}

// ---------------- Kernel 1b: G fp32 -> B fragments + gts norms ----------------
// Block = one 32-row group g of gts. Produces p = 2g, 2g+1 (two n16 blocks).
// Fragment (p, ks, lane l): 16B = {b0,b1 of mat0, b0,b1 of mat1}; mat m covers
// n8-block ni = 2*(p&1)+m; n-position j = l>>2 of block ni holds gts row
// g*32 + sigma(8*ni+j), sigma(8v+2u+e)=8u+2v+e (column involution so the GEMM
// epilogue's thread q owns 8 consecutive output columns).
__global__ void __launch_bounds__(256) bfrag_kernel(const float* __restrict__ G)
{
    __shared__ __align__(16) float sm[32 * 132];   // 528B rows (pad)
    int g = blockIdx.x;              // 0..511
    int t = threadIdx.x;
    int wid = t >> 5, lane = t & 31;

    // load 32 rows x 128 fp32 (1024 uint4)
    const uint4* src = (const uint4*)(G + (size_t)g * 32 * DHEAD);
    #pragma unroll
    for (int k = 0; k < 4; ++k) {
        int i = t + k * 256;
        int row = i >> 5, c = i & 31;
        *(uint4*)(sm + row * 132 + c * 4) = src[i];
    }
    __syncthreads();

    // row norms: warp w handles rows 4w..4w+3
    #pragma unroll
    for (int i = 0; i < 4; ++i) {
        int row = wid * 4 + i;
        float4 v = *(float4*)(sm + row * 132 + lane * 4);
        float s = v.x * v.x + v.y * v.y + v.z * v.z + v.w * v.w;
        #pragma unroll
        for (int o = 16; o > 0; o >>= 1) s += __shfl_xor_sync(0xFFFFFFFFu, s, o);
        if (lane == 0) g_gsq[g * 32 + row] = s;
    }

    // fragments: 2 p-blocks x 8 ks x 32 lanes = 512 units, 2 per thread
    #pragma unroll
    for (int k = 0; k < 2; ++k) {
        int u = t + k * 256;
        int pp = u >> 8;
        int ks = (u >> 5) & 7;
        int l = u & 31;
        int j = l >> 2;
        int kb = ks * 16 + (l & 3) * 2;          // k element base
        int r0 = 8 * (j >> 1) + 2 * (2 * pp + 0) + (j & 1);
        int r1 = 8 * (j >> 1) + 2 * (2 * pp + 1) + (j & 1);
        const float* R0 = sm + r0 * 132;
        const float* R1 = sm + r1 * 132;
        __nv_bfloat162 c0 = __float22bfloat162_rn(make_float2(R0[kb],     R0[kb + 1]));
        __nv_bfloat162 c1 = __float22bfloat162_rn(make_float2(R0[kb + 8], R0[kb + 9]));
        __nv_bfloat162 c2 = __float22bfloat162_rn(make_float2(R1[kb],     R1[kb + 1]));
        __nv_bfloat162 c3 = __float22bfloat162_rn(make_float2(R1[kb + 8], R1[kb + 9]));
        g_Bfrag[(((size_t)(2 * g + pp) * 8 + ks) * 32) + l] =
            make_uint4(*(uint32_t*)&c0, *(uint32_t*)&c1, *(uint32_t*)&c2, *(uint32_t*)&c3);
    }
}

// ---------------- Kernel 2: barrier-free staggered multi-tile HMMA ----------
// 256 threads, 8 warps 2Mx4N (warp 64x32). A tile (32KB) resident in SMEM
// (one barrier). B operands via LDG.128 from g_Bfrag with 2-step lookahead.
// NT=8 tiles per CTA; warp w walks tiles in order (w+t)&7 (phase staggering).
// A-FRAGMENT ROTATION: a[mi] is reloaded for ks+1 immediately after its 4
// HMMAs consume it (in-place, zero extra regs) -> A LDSM latency is always
// covered by ~12 in-flight HMMAs; asm volatile order enforces the schedule.

static constexpr int NT = 8;
static constexpr int SMEM_BYTES = 32768;

__device__ __forceinline__ void ldmatrix_x4(uint32_t* r, uint32_t addr) {
    asm volatile("ldmatrix.sync.aligned.m8n8.x4.shared.b16 {%0,%1,%2,%3}, [%4];"
                 : "=r"(r[0]), "=r"(r[1]), "=r"(r[2]), "=r"(r[3]) : "r"(addr));
}
__device__ __forceinline__ void mma_16816(float* d, const uint32_t* a, const uint32_t* b) {
    asm volatile(
        "mma.sync.aligned.m16n8k16.row.col.f32.bf16.bf16.f32 "
        "{%0,%1,%2,%3}, {%4,%5,%6,%7}, {%8,%9}, {%0,%1,%2,%3};"
        : "+f"(d[0]), "+f"(d[1]), "+f"(d[2]), "+f"(d[3])
        : "r"(a[0]), "r"(a[1]), "r"(a[2]), "r"(a[3]), "r"(b[0]), "r"(b[1]));
}
__device__ __forceinline__ void cp_async16(uint32_t smem_addr, const void* gptr) {
    asm volatile("cp.async.cg.shared.global [%0], [%1], 16;"
                 :: "r"(smem_addr), "l"(gptr) : "memory");
}

__global__ void __launch_bounds__(256, 2) l2_mma_kernel(float* __restrict__ out, int n_gts_total)
{
    extern __shared__ char smem[];
    uint32_t sAu = smem_u32(smem);

    int tid = threadIdx.x, wid = tid >> 5, lane = tid & 31;
    int ngrp = blockIdx.x;           // group of NT n-tiles
    int mtile = blockIdx.y;

    // ---- Prologue: resident A tile (swizzled SMEM), single barrier ----
    const char* Ag = (const char*)(g_Abf + (size_t)mtile * 128 * DHEAD);
    #pragma unroll
    for (int k = 0; k < 8; ++k) {
        int i = tid + k * 256;
        int r = i >> 4;
        int c16 = i & 15;
        uint32_t off = (uint32_t)r * 256u + ((uint32_t)(c16 ^ (r & 7)) << 4);
        cp_async16(sAu + off, Ag + i * 16);
    }
    asm volatile("cp.async.commit_group;" ::: "memory");
    asm volatile("cp.async.wait_group 0;" ::: "memory");
    __syncthreads();

    int wr = wid >> 2;   // 0..1  (M block of 64)
    int wc = wid & 3;    // 0..3  (N block of 32)
    int q = lane & 3;

    int row0 = mtile * 128 + wr * 64 + (lane >> 2);
    float xs[4][2];
    #pragma unroll
    for (int mi = 0; mi < 4; ++mi) {
        xs[mi][0] = g_xsq[row0 + mi * 16];
        xs[mi][1] = g_xsq[row0 + mi * 16 + 8];
    }

    const uint4* Bf = g_Bfrag;

    // A fragment smem addresses: row/swizzle part fixed per (wr,mi,lane)
    // addr(mi, ks) = base[mi] + ((ks*2 + hi) ^ (r&7)) * 16 ; precompute base+hi
    uint32_t aRow[4];
    #pragma unroll
    for (int mi = 0; mi < 4; ++mi) {
        int r = wr * 64 + mi * 16 + (lane & 15);
        aRow[mi] = sAu + (uint32_t)r * 256u;
    }
    int aHi = (lane >> 4);           // 0/1: which 16B half of the k-pair
    int aSw;
    {
        int r = (lane & 15);         // (r&7) only depends on lane&7 + mi*16(mult of 8)
        aSw = (wr * 64 + r) & 7;     // mi*16 doesn't change low 3 bits
    }

    // bootstrap: B slots 0,1 of first tile; A fragments for ks=0
    uint4 bq[4][2];
    {
        int p00 = (ngrp * NT + (wid & 7)) * 8 + wc * 2;
        #pragma unroll
        for (int s = 0; s < 2; ++s) {
            bq[s][0] = Bf[(size_t)((p00 + 0) * 8 + s) * 32 + lane];
            bq[s][1] = Bf[(size_t)((p00 + 1) * 8 + s) * 32 + lane];
        }
    }
    uint32_t a[4][4];
    #pragma unroll
    for (int mi = 0; mi < 4; ++mi)
        ldmatrix_x4(a[mi], aRow[mi] + ((uint32_t)((0 * 2 + aHi) ^ aSw) << 4));

    for (int t = 0; t < NT; ++t) {
        int tg = ngrp * NT + ((wid + t) & 7);       // staggered tile index
        int p0 = tg * 8 + wc * 2;
        int colbase = tg * 128 + wc * 32 + 8 * q;

        // hoist gsq loads: latency hides under the MMA loop
        float gs[4][2];
        #pragma unroll
        for (int ni = 0; ni < 4; ++ni) {
            float2 g2 = *(const float2*)(g_gsq + colbase + 2 * ni);
            gs[ni][0] = g2.x;
            gs[ni][1] = g2.y;
        }

        float d[4][4][4];
        #pragma unroll
        for (int mi = 0; mi < 4; ++mi)
            #pragma unroll
            for (int ni = 0; ni < 4; ++ni)
                #pragma unroll
                for (int j = 0; j < 4; ++j) d[mi][ni][j] = 0.0f;

        #pragma unroll
        for (int ks = 0; ks < 8; ++ks) {
            // B prefetch: step ks+2 (possibly this warp's next tile)
            if (ks < 6) {
                int ksp = ks + 2;
                bq[ksp & 3][0] = Bf[(size_t)((p0 + 0) * 8 + ksp) * 32 + lane];
                bq[ksp & 3][1] = Bf[(size_t)((p0 + 1) * 8 + ksp) * 32 + lane];
            } else if (t + 1 < NT) {
                int ksp = ks - 6;                   // next tile's ks 0/1
                int pn = (ngrp * NT + ((wid + t + 1) & 7)) * 8 + wc * 2;
                bq[(ks + 2) & 3][0] = Bf[(size_t)((pn + 0) * 8 + ksp) * 32 + lane];
                bq[(ks + 2) & 3][1] = Bf[(size_t)((pn + 1) * 8 + ksp) * 32 + lane];
            }

            const uint4 q0 = bq[ks & 3][0];
            const uint4 q1 = bq[ks & 3][1];
            uint32_t b[4][2] = {{q0.x, q0.y}, {q0.z, q0.w}, {q1.x, q1.y}, {q1.z, q1.w}};

            int ksn = (ks + 1) & 7;                 // next A k-step (wraps to 0)
            uint32_t aoff = (uint32_t)((ksn * 2 + aHi) ^ aSw) << 4;

            // rotation: consume a[mi] with its 4 HMMAs, then reload it for ksn
            #pragma unroll
            for (int mi = 0; mi < 4; ++mi) {
                mma_16816(d[mi][0], a[mi], b[0]);
                mma_16816(d[mi][1], a[mi], b[1]);
                mma_16816(d[mi][2], a[mi], b[2]);
                mma_16816(d[mi][3], a[mi], b[3]);
                ldmatrix_x4(a[mi], aRow[mi] + aoff);
            }
        }

        // ---- Epilogue tile tg: -sqrt(xsq + gsq - 2*xg)  (d2 >> 0, no clamp) -
        #pragma unroll
        for (int mi = 0; mi < 4; ++mi) {
            #pragma unroll
            for (int h = 0; h < 2; ++h) {
                float xv = xs[mi][h];
                float v[8];
                #pragma unroll
                for (int ni = 0; ni < 4; ++ni) {
                    float d20 = fmaf(-2.0f, d[mi][ni][h * 2 + 0], xv + gs[ni][0]);
                    float d21 = fmaf(-2.0f, d[mi][ni][h * 2 + 1], xv + gs[ni][1]);
                    float r0, r1;
                    asm("sqrt.approx.f32 %0, %1;" : "=f"(r0) : "f"(d20));
                    asm("sqrt.approx.f32 %0, %1;" : "=f"(r1) : "f"(d21));
                    v[2 * ni]     = __uint_as_float(__float_as_uint(r0) | 0x80000000u);
                    v[2 * ni + 1] = __uint_as_float(__float_as_uint(r1) | 0x80000000u);
                }
                int grow = row0 + mi * 16 + h * 8;
                float* op = out + (size_t)grow * (size_t)n_gts_total + (size_t)colbase;
                *(float4*)(op)     = make_float4(v[0], v[1], v[2], v[3]);
                *(float4*)(op + 4) = make_float4(v[4], v[5], v[6], v[7]);
            }
        }
    }
}

// ---------------- Launch ----------------
extern "C" void kernel_launch(void* const* d_in, const int* in_sizes, int n_in,
                              void* d_out, int out_size)
{
    const float* X = (const float*)d_in[0];   // image_features [8192,128]
    const float* G = (const float*)d_in[1];   // gts            [16384,128]
    float* out = (float*)d_out;               // [8192,16384] fp32

    int n_img = in_sizes[0] / DHEAD;
    int n_gts = in_sizes[1] / DHEAD;

    convert_x_kernel<<<(n_img * 32 + 255) / 256, 256>>>(X, n_img);
    bfrag_kernel<<<n_gts / 32, 256>>>(G);

    cudaFuncSetAttribute(l2_mma_kernel, cudaFuncAttributeMaxDynamicSharedMemorySize, SMEM_BYTES);
    dim3 grid(n_gts / (128 * NT), n_img / 128);
    l2_mma_kernel<<<grid, 256, SMEM_BYTES>>>(out, n_gts);
}

// round 15
// speedup vs baseline: 1.0393x; 1.0393x over previous
#include <cuda_runtime.h>
#include <cuda_bf16.h>
#include <cstdint>

#define DHEAD 128

// Scratch (no runtime allocation allowed)
__device__ __nv_bfloat16 g_Abf[8192 * DHEAD];
__device__ float g_xsq[8192];
__device__ float g_gsq[16384];
// B in mma-fragment layout: [n16 block p][ks][lane] x 16B
__device__ uint4 g_Bfrag[1024 * 8 * 32];

__device__ __forceinline__ uint32_t smem_u32(const void* p) {
    uint32_t a;
    asm("{ .reg .u64 t; cvta.to.shared.u64 t, %1; cvt.u32.u64 %0, t; }" : "=r"(a) : "l"(p));
    return a;
}

// ---------------- Kernel 1: X fp32 -> bf16 + row norms ----------------
__global__ void __launch_bounds__(256) convert_x_kernel(const float* __restrict__ X, int n_img)
{
    int gw = (blockIdx.x * blockDim.x + threadIdx.x) >> 5;
    int lane = threadIdx.x & 31;
    if (gw >= n_img) return;
    const float4* src = (const float4*)(X + (size_t)gw * DHEAD);
    uint2* dst = (uint2*)(g_Abf + (size_t)gw * DHEAD);
    float4 v = src[lane];
    float s = v.x * v.x + v.y * v.y + v.z * v.z + v.w * v.w;
    #pragma unroll
    for (int o = 16; o > 0; o >>= 1) s += __shfl_xor_sync(0xFFFFFFFFu, s, o);
    __nv_bfloat162 p0 = __float22bfloat162_rn(make_float2(v.x, v.y));
    __nv_bfloat162 p1 = __float22bfloat162_rn(make_float2(v.z, v.w));
    uint2 o2;
    o2.x = *reinterpret_cast<uint32_t*>(&p0);
    o2.y = *reinterpret_cast<uint32_t*>(&p1);
    dst[lane] = o2;
    if (lane == 0) g_xsq[gw] = s;
}

// ---------------- Kernel 1b: G fp32 -> B fragments + gts norms ----------------
// Block = one 32-row group g of gts. Produces p = 2g, 2g+1 (two n16 blocks).
// Fragment (p, ks, lane l): 16B = {b0,b1 of mat0, b0,b1 of mat1}; mat m covers
// n8-block ni = 2*(p&1)+m; n-position j = l>>2 of block ni holds gts row
// g*32 + sigma(8*ni+j), sigma(8v+2u+e)=8u+2v+e (column involution so the GEMM
// epilogue's thread q owns 8 consecutive output columns).
__global__ void __launch_bounds__(256) bfrag_kernel(const float* __restrict__ G)
{
    __shared__ __align__(16) float sm[32 * 132];   // 528B rows (pad)
    int g = blockIdx.x;              // 0..511
    int t = threadIdx.x;
    int wid = t >> 5, lane = t & 31;

    // load 32 rows x 128 fp32 (1024 uint4)
    const uint4* src = (const uint4*)(G + (size_t)g * 32 * DHEAD);
    #pragma unroll
    for (int k = 0; k < 4; ++k) {
        int i = t + k * 256;
        int row = i >> 5, c = i & 31;
        *(uint4*)(sm + row * 132 + c * 4) = src[i];
    }
    __syncthreads();

    // row norms: warp w handles rows 4w..4w+3
    #pragma unroll
    for (int i = 0; i < 4; ++i) {
        int row = wid * 4 + i;
        float4 v = *(float4*)(sm + row * 132 + lane * 4);
        float s = v.x * v.x + v.y * v.y + v.z * v.z + v.w * v.w;
        #pragma unroll
        for (int o = 16; o > 0; o >>= 1) s += __shfl_xor_sync(0xFFFFFFFFu, s, o);
        if (lane == 0) g_gsq[g * 32 + row] = s;
    }

    // fragments: 2 p-blocks x 8 ks x 32 lanes = 512 units, 2 per thread
    #pragma unroll
    for (int k = 0; k < 2; ++k) {
        int u = t + k * 256;
        int pp = u >> 8;
        int ks = (u >> 5) & 7;
        int l = u & 31;
        int j = l >> 2;
        int kb = ks * 16 + (l & 3) * 2;          // k element base
        int r0 = 8 * (j >> 1) + 2 * (2 * pp + 0) + (j & 1);
        int r1 = 8 * (j >> 1) + 2 * (2 * pp + 1) + (j & 1);
        const float* R0 = sm + r0 * 132;
        const float* R1 = sm + r1 * 132;
        __nv_bfloat162 c0 = __float22bfloat162_rn(make_float2(R0[kb],     R0[kb + 1]));
        __nv_bfloat162 c1 = __float22bfloat162_rn(make_float2(R0[kb + 8], R0[kb + 9]));
        __nv_bfloat162 c2 = __float22bfloat162_rn(make_float2(R1[kb],     R1[kb + 1]));
        __nv_bfloat162 c3 = __float22bfloat162_rn(make_float2(R1[kb + 8], R1[kb + 9]));
        g_Bfrag[(((size_t)(2 * g + pp) * 8 + ks) * 32) + l] =
            make_uint4(*(uint32_t*)&c0, *(uint32_t*)&c1, *(uint32_t*)&c2, *(uint32_t*)&c3);
    }
}

// ---------------- Kernel 2: barrier-free staggered multi-tile HMMA ----------
// 256 threads, 8 warps 2Mx4N (warp 64x32). A tile (32KB) resident in SMEM
// (one barrier). B operands via LDG.128 from g_Bfrag with 3-step lookahead.
// NT=8 tiles per CTA; warp w walks tiles in order (w+t)&7 (phase staggering).
// Inner loop = R12 form (batch 4 A-LDSM then 16 HMMA) -- the forced rotation
// of R13 regressed and is reverted. gsq loads hoisted above the ks loop.

static constexpr int NT = 8;
static constexpr int SMEM_BYTES = 32768;

__device__ __forceinline__ void ldmatrix_x4(uint32_t* r, uint32_t addr) {
    asm volatile("ldmatrix.sync.aligned.m8n8.x4.shared.b16 {%0,%1,%2,%3}, [%4];"
                 : "=r"(r[0]), "=r"(r[1]), "=r"(r[2]), "=r"(r[3]) : "r"(addr));
}
__device__ __forceinline__ void mma_16816(float* d, const uint32_t* a, const uint32_t* b) {
    asm volatile(
        "mma.sync.aligned.m16n8k16.row.col.f32.bf16.bf16.f32 "
        "{%0,%1,%2,%3}, {%4,%5,%6,%7}, {%8,%9}, {%0,%1,%2,%3};"
        : "+f"(d[0]), "+f"(d[1]), "+f"(d[2]), "+f"(d[3])
        : "r"(a[0]), "r"(a[1]), "r"(a[2]), "r"(a[3]), "r"(b[0]), "r"(b[1]));
}
__device__ __forceinline__ void cp_async16(uint32_t smem_addr, const void* gptr) {
    asm volatile("cp.async.cg.shared.global [%0], [%1], 16;"
                 :: "r"(smem_addr), "l"(gptr) : "memory");
}

__global__ void __launch_bounds__(256, 2) l2_mma_kernel(float* __restrict__ out, int n_gts_total)
{
    extern __shared__ char smem[];
    uint32_t sAu = smem_u32(smem);

    int tid = threadIdx.x, wid = tid >> 5, lane = tid & 31;
    int ngrp = blockIdx.x;           // group of NT n-tiles
    int mtile = blockIdx.y;

    // ---- Prologue: resident A tile (swizzled SMEM), single barrier ----
    const char* Ag = (const char*)(g_Abf + (size_t)mtile * 128 * DHEAD);
    #pragma unroll
    for (int k = 0; k < 8; ++k) {
        int i = tid + k * 256;
        int r = i >> 4;
        int c16 = i & 15;
        uint32_t off = (uint32_t)r * 256u + ((uint32_t)(c16 ^ (r & 7)) << 4);
        cp_async16(sAu + off, Ag + i * 16);
    }
    asm volatile("cp.async.commit_group;" ::: "memory");
    asm volatile("cp.async.wait_group 0;" ::: "memory");
    __syncthreads();

    int wr = wid >> 2;   // 0..1  (M block of 64)
    int wc = wid & 3;    // 0..3  (N block of 32)
    int q = lane & 3;

    int row0 = mtile * 128 + wr * 64 + (lane >> 2);
    float xs[4][2];
    #pragma unroll
    for (int mi = 0; mi < 4; ++mi) {
        xs[mi][0] = g_xsq[row0 + mi * 16];
        xs[mi][1] = g_xsq[row0 + mi * 16 + 8];
    }

    const uint4* Bf = g_Bfrag;

    // bootstrap: B slots 0,1,2 of this warp's first tile
    uint4 bq[4][2];
    {
        int p00 = (ngrp * NT + (wid & 7)) * 8 + wc * 2;
        #pragma unroll
        for (int s = 0; s < 3; ++s) {
            bq[s][0] = Bf[(size_t)((p00 + 0) * 8 + s) * 32 + lane];
            bq[s][1] = Bf[(size_t)((p00 + 1) * 8 + s) * 32 + lane];
        }
    }

    for (int t = 0; t < NT; ++t) {
        int tg = ngrp * NT + ((wid + t) & 7);       // staggered tile index
        int p0 = tg * 8 + wc * 2;
        int colbase = tg * 128 + wc * 32 + 8 * q;

        // hoist gsq loads: latency hides under the MMA loop
        float gs[4][2];
        #pragma unroll
        for (int ni = 0; ni < 4; ++ni) {
            float2 g2 = *(const float2*)(g_gsq + colbase + 2 * ni);
            gs[ni][0] = g2.x;
            gs[ni][1] = g2.y;
        }

        float d[4][4][4];
        #pragma unroll
        for (int mi = 0; mi < 4; ++mi)
            #pragma unroll
            for (int ni = 0; ni < 4; ++ni)
                #pragma unroll
                for (int j = 0; j < 4; ++j) d[mi][ni][j] = 0.0f;

        #pragma unroll
        for (int ks = 0; ks < 8; ++ks) {
            // B prefetch, distance 3: step ks+3 (possibly this warp's next tile)
            if (ks < 5) {
                int ksp = ks + 3;
                bq[ksp & 3][0] = Bf[(size_t)((p0 + 0) * 8 + ksp) * 32 + lane];
                bq[ksp & 3][1] = Bf[(size_t)((p0 + 1) * 8 + ksp) * 32 + lane];
            } else if (t + 1 < NT) {
                int ksp = ks - 5;                   // next tile's ks 0/1/2
                int pn = (ngrp * NT + ((wid + t + 1) & 7)) * 8 + wc * 2;
                bq[(ks + 3) & 3][0] = Bf[(size_t)((pn + 0) * 8 + ksp) * 32 + lane];
                bq[(ks + 3) & 3][1] = Bf[(size_t)((pn + 1) * 8 + ksp) * 32 + lane];
            }

            uint32_t a[4][4];
            #pragma unroll
            for (int mi = 0; mi < 4; ++mi) {
                int r = wr * 64 + mi * 16 + (lane & 15);
                int kc = ks * 2 + (lane >> 4);
                uint32_t addr = sAu + (uint32_t)r * 256u + ((uint32_t)(kc ^ (r & 7)) << 4);
                ldmatrix_x4(a[mi], addr);
            }
            const uint4 q0 = bq[ks & 3][0];
            const uint4 q1 = bq[ks & 3][1];
            uint32_t b[4][2] = {{q0.x, q0.y}, {q0.z, q0.w}, {q1.x, q1.y}, {q1.z, q1.w}};

            #pragma unroll
            for (int mi = 0; mi < 4; ++mi)
                #pragma unroll
                for (int ni = 0; ni < 4; ++ni)
                    mma_16816(d[mi][ni], a[mi], b[ni]);
        }

        // ---- Epilogue tile tg: -sqrt(xsq + gsq - 2*xg)  (d2 >> 0, no clamp) -
        #pragma unroll
        for (int mi = 0; mi < 4; ++mi) {
            #pragma unroll
            for (int h = 0; h < 2; ++h) {
                float xv = xs[mi][h];
                float v[8];
                #pragma unroll
                for (int ni = 0; ni < 4; ++ni) {
                    float d20 = fmaf(-2.0f, d[mi][ni][h * 2 + 0], xv + gs[ni][0]);
                    float d21 = fmaf(-2.0f, d[mi][ni][h * 2 + 1], xv + gs[ni][1]);
                    float r0, r1;
                    asm("sqrt.approx.f32 %0, %1;" : "=f"(r0) : "f"(d20));
                    asm("sqrt.approx.f32 %0, %1;" : "=f"(r1) : "f"(d21));
                    v[2 * ni]     = __uint_as_float(__float_as_uint(r0) | 0x80000000u);
                    v[2 * ni + 1] = __uint_as_float(__float_as_uint(r1) | 0x80000000u);
                }
                int grow = row0 + mi * 16 + h * 8;
                float* op = out + (size_t)grow * (size_t)n_gts_total + (size_t)colbase;
                *(float4*)(op)     = make_float4(v[0], v[1], v[2], v[3]);
                *(float4*)(op + 4) = make_float4(v[4], v[5], v[6], v[7]);
            }
        }
    }
}

// ---------------- Launch ----------------
extern "C" void kernel_launch(void* const* d_in, const int* in_sizes, int n_in,
                              void* d_out, int out_size)
{
    const float* X = (const float*)d_in[0];   // image_features [8192,128]
    const float* G = (const float*)d_in[1];   // gts            [16384,128]
    float* out = (float*)d_out;               // [8192,16384] fp32

    int n_img = in_sizes[0] / DHEAD;
    int n_gts = in_sizes[1] / DHEAD;

    convert_x_kernel<<<(n_img * 32 + 255) / 256, 256>>>(X, n_img);
    bfrag_kernel<<<n_gts / 32, 256>>>(G);

    cudaFuncSetAttribute(l2_mma_kernel, cudaFuncAttributeMaxDynamicSharedMemorySize, SMEM_BYTES);
    dim3 grid(n_gts / (128 * NT), n_img / 128);
    l2_mma_kernel<<<grid, 256, SMEM_BYTES>>>(out, n_gts);
}

// round 16
// speedup vs baseline: 1.2849x; 1.2363x over previous
#include <cuda_runtime.h>
#include <cuda_bf16.h>
#include <cstdint>

#define DHEAD 128

// Scratch (no runtime allocation allowed)
__device__ __nv_bfloat16 g_Abf[8192 * DHEAD];
__device__ float g_xsq[8192];
__device__ float g_gsq[16384];
// B in mma-fragment layout: [n16 block p][ks][lane] x 16B
__device__ uint4 g_Bfrag[1024 * 8 * 32];

__device__ __forceinline__ uint32_t smem_u32(const void* p) {
    uint32_t a;
    asm("{ .reg .u64 t; cvta.to.shared.u64 t, %1; cvt.u32.u64 %0, t; }" : "=r"(a) : "l"(p));
    return a;
}

// ---------------- Kernel 1 (fused pre-pass) ----------------
// Blocks [0, nG) : G fp32 -> B fragments + gts norms (one 32-row group each)
// Blocks [nG, nG + nXblocks) : X fp32 -> bf16 + row norms (8 rows per block)
//
// B fragment layout: block g produces p = 2g, 2g+1 (two n16 blocks).
// Fragment (p, ks, lane l): 16B = {b0,b1 of mat0, b0,b1 of mat1}; mat m covers
// n8-block ni = 2*(p&1)+m; n-position j = l>>2 of block ni holds gts row
// g*32 + sigma(8*ni+j), sigma(8v+2u+e)=8u+2v+e (column involution so the GEMM
// epilogue's thread q owns 8 consecutive output columns).
__global__ void __launch_bounds__(256) prepass_kernel(
    const float* __restrict__ X, const float* __restrict__ G, int nG, int n_img)
{
    __shared__ __align__(16) float sm[32 * 132];   // 528B rows (pad)
    int blk = blockIdx.x;
    int t = threadIdx.x;
    int wid = t >> 5, lane = t & 31;

    if (blk >= nG) {
        // ---- X convert: 8 rows (one per warp) ----
        int gw = (blk - nG) * 8 + wid;
        if (gw < n_img) {
            const float4* src = (const float4*)(X + (size_t)gw * DHEAD);
            uint2* dst = (uint2*)(g_Abf + (size_t)gw * DHEAD);
            float4 v = src[lane];
            float s = v.x * v.x + v.y * v.y + v.z * v.z + v.w * v.w;
            #pragma unroll
            for (int o = 16; o > 0; o >>= 1) s += __shfl_xor_sync(0xFFFFFFFFu, s, o);
            __nv_bfloat162 p0 = __float22bfloat162_rn(make_float2(v.x, v.y));
            __nv_bfloat162 p1 = __float22bfloat162_rn(make_float2(v.z, v.w));
            uint2 o2;
            o2.x = *reinterpret_cast<uint32_t*>(&p0);
            o2.y = *reinterpret_cast<uint32_t*>(&p1);
            dst[lane] = o2;
            if (lane == 0) g_xsq[gw] = s;
        }
        return;
    }

    int g = blk;                     // 0..nG-1

    // load 32 rows x 128 fp32 (1024 uint4)
    const uint4* src = (const uint4*)(G + (size_t)g * 32 * DHEAD);
    #pragma unroll
    for (int k = 0; k < 4; ++k) {
        int i = t + k * 256;
        int row = i >> 5, c = i & 31;
        *(uint4*)(sm + row * 132 + c * 4) = src[i];
    }
    __syncthreads();

    // row norms: warp w handles rows 4w..4w+3
    #pragma unroll
    for (int i = 0; i < 4; ++i) {
        int row = wid * 4 + i;
        float4 v = *(float4*)(sm + row * 132 + lane * 4);
        float s = v.x * v.x + v.y * v.y + v.z * v.z + v.w * v.w;
        #pragma unroll
        for (int o = 16; o > 0; o >>= 1) s += __shfl_xor_sync(0xFFFFFFFFu, s, o);
        if (lane == 0) g_gsq[g * 32 + row] = s;
    }

    // fragments: 2 p-blocks x 8 ks x 32 lanes = 512 units, 2 per thread
    #pragma unroll
    for (int k = 0; k < 2; ++k) {
        int u = t + k * 256;
        int pp = u >> 8;
        int ks = (u >> 5) & 7;
        int l = u & 31;
        int j = l >> 2;
        int kb = ks * 16 + (l & 3) * 2;          // k element base
        int r0 = 8 * (j >> 1) + 2 * (2 * pp + 0) + (j & 1);
        int r1 = 8 * (j >> 1) + 2 * (2 * pp + 1) + (j & 1);
        const float* R0 = sm + r0 * 132;
        const float* R1 = sm + r1 * 132;
        __nv_bfloat162 c0 = __float22bfloat162_rn(make_float2(R0[kb],     R0[kb + 1]));
        __nv_bfloat162 c1 = __float22bfloat162_rn(make_float2(R0[kb + 8], R0[kb + 9]));
        __nv_bfloat162 c2 = __float22bfloat162_rn(make_float2(R1[kb],     R1[kb + 1]));
        __nv_bfloat162 c3 = __float22bfloat162_rn(make_float2(R1[kb + 8], R1[kb + 9]));
        g_Bfrag[(((size_t)(2 * g + pp) * 8 + ks) * 32) + l] =
            make_uint4(*(uint32_t*)&c0, *(uint32_t*)&c1, *(uint32_t*)&c2, *(uint32_t*)&c3);
    }
}

// ---------------- Kernel 2: barrier-free staggered multi-tile HMMA ----------
// (byte-identical inner structure to the 149.4us R12 kernel)
// 256 threads, 8 warps 2Mx4N (warp 64x32). A tile (32KB) resident in SMEM
// (one barrier). B operands via LDG.128 from g_Bfrag with 2-step lookahead.
// NT=8 tiles per CTA; warp w walks tiles in order (w+t)&7 (phase staggering).

static constexpr int NT = 8;
static constexpr int SMEM_BYTES = 32768;

__device__ __forceinline__ void ldmatrix_x4(uint32_t* r, uint32_t addr) {
    asm volatile("ldmatrix.sync.aligned.m8n8.x4.shared.b16 {%0,%1,%2,%3}, [%4];"
                 : "=r"(r[0]), "=r"(r[1]), "=r"(r[2]), "=r"(r[3]) : "r"(addr));
}
__device__ __forceinline__ void mma_16816(float* d, const uint32_t* a, const uint32_t* b) {
    asm volatile(
        "mma.sync.aligned.m16n8k16.row.col.f32.bf16.bf16.f32 "
        "{%0,%1,%2,%3}, {%4,%5,%6,%7}, {%8,%9}, {%0,%1,%2,%3};"
        : "+f"(d[0]), "+f"(d[1]), "+f"(d[2]), "+f"(d[3])
        : "r"(a[0]), "r"(a[1]), "r"(a[2]), "r"(a[3]), "r"(b[0]), "r"(b[1]));
}
__device__ __forceinline__ void cp_async16(uint32_t smem_addr, const void* gptr) {
    asm volatile("cp.async.cg.shared.global [%0], [%1], 16;"
                 :: "r"(smem_addr), "l"(gptr) : "memory");
}

__global__ void __launch_bounds__(256, 2) l2_mma_kernel(float* __restrict__ out, int n_gts_total)
{
    extern __shared__ char smem[];
    uint32_t sAu = smem_u32(smem);

    int tid = threadIdx.x, wid = tid >> 5, lane = tid & 31;
    int ngrp = blockIdx.x;           // group of NT n-tiles
    int mtile = blockIdx.y;

    // ---- Prologue: resident A tile (swizzled SMEM), single barrier ----
    const char* Ag = (const char*)(g_Abf + (size_t)mtile * 128 * DHEAD);
    #pragma unroll
    for (int k = 0; k < 8; ++k) {
        int i = tid + k * 256;
        int r = i >> 4;
        int c16 = i & 15;
        uint32_t off = (uint32_t)r * 256u + ((uint32_t)(c16 ^ (r & 7)) << 4);
        cp_async16(sAu + off, Ag + i * 16);
    }
    asm volatile("cp.async.commit_group;" ::: "memory");
    asm volatile("cp.async.wait_group 0;" ::: "memory");
    __syncthreads();

    int wr = wid >> 2;   // 0..1  (M block of 64)
    int wc = wid & 3;    // 0..3  (N block of 32)
    int q = lane & 3;

    int row0 = mtile * 128 + wr * 64 + (lane >> 2);
    float xs[4][2];
    #pragma unroll
    for (int mi = 0; mi < 4; ++mi) {
        xs[mi][0] = g_xsq[row0 + mi * 16];
        xs[mi][1] = g_xsq[row0 + mi * 16 + 8];
    }

    const uint4* Bf = g_Bfrag;

    // bootstrap: B slots 0,1 of this warp's first tile
    uint4 bq[4][2];
    {
        int p00 = (ngrp * NT + (wid & 7)) * 8 + wc * 2;
        #pragma unroll
        for (int s = 0; s < 2; ++s) {
            bq[s][0] = Bf[(size_t)((p00 + 0) * 8 + s) * 32 + lane];
            bq[s][1] = Bf[(size_t)((p00 + 1) * 8 + s) * 32 + lane];
        }
    }

    for (int t = 0; t < NT; ++t) {
        int tg = ngrp * NT + ((wid + t) & 7);       // staggered tile index
        int p0 = tg * 8 + wc * 2;

        float d[4][4][4];
        #pragma unroll
        for (int mi = 0; mi < 4; ++mi)
            #pragma unroll
            for (int ni = 0; ni < 4; ++ni)
                #pragma unroll
                for (int j = 0; j < 4; ++j) d[mi][ni][j] = 0.0f;

        #pragma unroll
        for (int ks = 0; ks < 8; ++ks) {
            // B prefetch: step ks+2 (possibly this warp's next tile)
            if (ks < 6) {
                int ksp = ks + 2;
                bq[ksp & 3][0] = Bf[(size_t)((p0 + 0) * 8 + ksp) * 32 + lane];
                bq[ksp & 3][1] = Bf[(size_t)((p0 + 1) * 8 + ksp) * 32 + lane];
            } else if (t + 1 < NT) {
                int ksp = ks - 6;                   // next tile's ks 0/1
                int pn = (ngrp * NT + ((wid + t + 1) & 7)) * 8 + wc * 2;
                bq[(ks + 2) & 3][0] = Bf[(size_t)((pn + 0) * 8 + ksp) * 32 + lane];
                bq[(ks + 2) & 3][1] = Bf[(size_t)((pn + 1) * 8 + ksp) * 32 + lane];
            }

            uint32_t a[4][4];
            #pragma unroll
            for (int mi = 0; mi < 4; ++mi) {
                int r = wr * 64 + mi * 16 + (lane & 15);
                int kc = ks * 2 + (lane >> 4);
                uint32_t addr = sAu + (uint32_t)r * 256u + ((uint32_t)(kc ^ (r & 7)) << 4);
                ldmatrix_x4(a[mi], addr);
            }
            const uint4 q0 = bq[ks & 3][0];
            const uint4 q1 = bq[ks & 3][1];
            uint32_t b[4][2] = {{q0.x, q0.y}, {q0.z, q0.w}, {q1.x, q1.y}, {q1.z, q1.w}};

            #pragma unroll
            for (int mi = 0; mi < 4; ++mi)
                #pragma unroll
                for (int ni = 0; ni < 4; ++ni)
                    mma_16816(d[mi][ni], a[mi], b[ni]);
        }

        // ---- Epilogue tile tg: -sqrt(xsq + gsq - 2*xg)  (d2 >> 0, no clamp) -
        int colbase = tg * 128 + wc * 32 + 8 * q;
        float gs[4][2];
        #pragma unroll
        for (int ni = 0; ni < 4; ++ni) {
            float2 g2 = *(const float2*)(g_gsq + colbase + 2 * ni);
            gs[ni][0] = g2.x;
            gs[ni][1] = g2.y;
        }

        #pragma unroll
        for (int mi = 0; mi < 4; ++mi) {
            #pragma unroll
            for (int h = 0; h < 2; ++h) {
                float xv = xs[mi][h];
                float v[8];
                #pragma unroll
                for (int ni = 0; ni < 4; ++ni) {
                    float d20 = fmaf(-2.0f, d[mi][ni][h * 2 + 0], xv + gs[ni][0]);
                    float d21 = fmaf(-2.0f, d[mi][ni][h * 2 + 1], xv + gs[ni][1]);
                    float r0, r1;
                    asm("sqrt.approx.f32 %0, %1;" : "=f"(r0) : "f"(d20));
                    asm("sqrt.approx.f32 %0, %1;" : "=f"(r1) : "f"(d21));
                    v[2 * ni]     = __uint_as_float(__float_as_uint(r0) | 0x80000000u);
                    v[2 * ni + 1] = __uint_as_float(__float_as_uint(r1) | 0x80000000u);
                }
                int grow = row0 + mi * 16 + h * 8;
                float* op = out + (size_t)grow * (size_t)n_gts_total + (size_t)colbase;
                *(float4*)(op)     = make_float4(v[0], v[1], v[2], v[3]);
                *(float4*)(op + 4) = make_float4(v[4], v[5], v[6], v[7]);
            }
        }
    }
}

// ---------------- Launch ----------------
extern "C" void kernel_launch(void* const* d_in, const int* in_sizes, int n_in,
                              void* d_out, int out_size)
{
    const float* X = (const float*)d_in[0];   // image_features [8192,128]
    const float* G = (const float*)d_in[1];   // gts            [16384,128]
    float* out = (float*)d_out;               // [8192,16384] fp32

    int n_img = in_sizes[0] / DHEAD;
    int n_gts = in_sizes[1] / DHEAD;

    int nG = n_gts / 32;                       // 512 fragment blocks
    int nX = (n_img + 7) / 8;                  // 1024 convert blocks
    prepass_kernel<<<nG + nX, 256>>>(X, G, nG, n_img);

    cudaFuncSetAttribute(l2_mma_kernel, cudaFuncAttributeMaxDynamicSharedMemorySize, SMEM_BYTES);
    dim3 grid(n_gts / (128 * NT), n_img / 128);
    l2_mma_kernel<<<grid, 256, SMEM_BYTES>>>(out, n_gts);
}